// round 16
// baseline (speedup 1.0000x reference)
#include <cuda_runtime.h>
#include <cuda_bf16.h>
#include <cstdint>
#include <math.h>

#define BATCH 64
#define SEQ   512
#define INSZ  512
#define HSZ   512
#define G4    2048   // 4*HSZ
#define NCTA  128
#define GRP   32     // CTAs per bt-group barrier

// ---------------- scratch (device globals; no allocation allowed) ----------
__device__ float g_xproj[(size_t)BATCH * SEQ * G4];      // x @ W_ih fp32
__device__ unsigned g_cnt4[4][32];                       // group counters
__device__ __nv_bfloat16 g_xh[(size_t)BATCH * SEQ * INSZ];   // x hi
__device__ __nv_bfloat16 g_xl[(size_t)BATCH * SEQ * INSZ];   // x lo
__device__ __nv_bfloat16 g_wth[(size_t)G4 * INSZ];           // W_ih^T hi [n][k]
__device__ __nv_bfloat16 g_wtl[(size_t)G4 * INSZ];           // W_ih^T lo
__device__ __nv_bfloat16 g_whh_h[(size_t)G4 * HSZ];          // W_hh rearranged hi [cg][k]
__device__ __nv_bfloat16 g_whh_l[(size_t)G4 * HSZ];          // W_hh rearranged lo
__device__ __nv_bfloat16 g_hbh[2][BATCH * HSZ];              // h hi ping-pong [b][j]
__device__ __nv_bfloat16 g_hbl[2][BATCH * HSZ];              // h lo ping-pong [b][j]

// ---------------- fast activations -----------------------------------------
__device__ __forceinline__ float ex2f(float x) {
    float y; asm("ex2.approx.f32 %0, %1;" : "=f"(y) : "f"(x)); return y;
}
__device__ __forceinline__ float rcpf(float x) {
    float y; asm("rcp.approx.f32 %0, %1;" : "=f"(y) : "f"(x)); return y;
}
#define LOG2E 1.4426950408889634f
__device__ __forceinline__ float fast_sigmoid(float x) {
    return rcpf(1.0f + ex2f(-x * LOG2E));
}
__device__ __forceinline__ float fast_tanh(float x) {
    float a = fabsf(x);
    float t = ex2f(-2.0f * LOG2E * a);
    float r = 1.0f - 2.0f * t * rcpf(1.0f + t);
    return copysignf(r, x);
}

// ---------------- mma.sync / ldmatrix / cp.async helpers (plain sm_103) ----
__device__ __forceinline__ uint32_t smem_u32(const void* p) {
    uint32_t a;
    asm("{ .reg .u64 t; cvta.to.shared.u64 t, %1; cvt.u32.u64 %0, t; }"
        : "=r"(a) : "l"(p));
    return a;
}
__device__ __forceinline__ void ldsm4(uint32_t addr, uint32_t r[4]) {
    asm volatile("ldmatrix.sync.aligned.m8n8.x4.shared.b16 {%0,%1,%2,%3}, [%4];"
                 : "=r"(r[0]), "=r"(r[1]), "=r"(r[2]), "=r"(r[3]) : "r"(addr));
}
__device__ __forceinline__ void ldsm2(uint32_t addr, uint32_t& r0, uint32_t& r1) {
    asm volatile("ldmatrix.sync.aligned.m8n8.x2.shared.b16 {%0,%1}, [%2];"
                 : "=r"(r0), "=r"(r1) : "r"(addr));
}
__device__ __forceinline__ void mma16816(float c[4], const uint32_t a[4],
                                         uint32_t b0, uint32_t b1) {
    asm volatile(
        "mma.sync.aligned.m16n8k16.row.col.f32.bf16.bf16.f32 "
        "{%0,%1,%2,%3}, {%4,%5,%6,%7}, {%8,%9}, {%0,%1,%2,%3};"
        : "+f"(c[0]), "+f"(c[1]), "+f"(c[2]), "+f"(c[3])
        : "r"(a[0]), "r"(a[1]), "r"(a[2]), "r"(a[3]), "r"(b0), "r"(b1));
}
#define CP16(s, g) asm volatile("cp.async.cg.shared.global [%0], [%1], 16;" :: "r"(s), "l"(g))
#define CPCOMMIT() asm volatile("cp.async.commit_group;" ::: "memory")
#define CPWAIT(n)  asm volatile("cp.async.wait_group %0;" :: "n"(n) : "memory")

__device__ __forceinline__ void st_bf16_cg(__nv_bfloat16* p, __nv_bfloat16 v) {
    unsigned short u = *reinterpret_cast<unsigned short*>(&v);
    asm volatile("st.global.cg.u16 [%0], %1;" :: "l"(p), "h"(u) : "memory");
}

// ---------------- prologue conversions -------------------------------------
__global__ void conv_x(const float* __restrict__ X) {
    size_t i = (size_t)blockIdx.x * blockDim.x + threadIdx.x;
    float v = X[i];
    __nv_bfloat16 h = __float2bfloat16(v);
    g_xh[i] = h;
    g_xl[i] = __float2bfloat16(v - __bfloat162float(h));
}
__global__ void conv_w(const float* __restrict__ Wih) {
    int idx = blockIdx.x * blockDim.x + threadIdx.x;
    int k = idx >> 11, n = idx & 2047;
    float v = Wih[idx];
    __nv_bfloat16 h = __float2bfloat16(v);
    g_wth[(size_t)n * INSZ + k] = h;
    g_wtl[(size_t)n * INSZ + k] = __float2bfloat16(v - __bfloat162float(h));
}
// W_hh col-reorder for warp-local gates: source col = gate*512 + jt*16 + jl.
// cg = jt*64 + (jl>>1)*8 + (jl&1)*4 + gate  -> warp (jl>>1) owns 8 cols =
// [i,f,g,o] of j-pair (jl&1). Layout [cg][k].
__global__ void conv_whh(const float* __restrict__ Whh) {
    int idx = blockIdx.x * blockDim.x + threadIdx.x;  // k*2048 + col
    int k = idx >> 11, col = idx & 2047;
    int gate = col >> 9, rem = col & 511;
    int jt = rem >> 4, jl = rem & 15;
    size_t cg = (size_t)(jt * 64 + (jl >> 1) * 8 + (jl & 1) * 4 + gate);
    float v = Whh[idx];
    __nv_bfloat16 h = __float2bfloat16(v);
    g_whh_h[cg * HSZ + k] = h;
    g_whh_l[cg * HSZ + k] = __float2bfloat16(v - __bfloat162float(h));
}

// ---------------- kernel 1: x_proj via mma.sync (R14 proven) ---------------
#define ROWB   144
#define ATILEB (128 * ROWB)
#define BTILEB (64 * ROWB)
#define BUFB   (2 * ATILEB + 2 * BTILEB)
#define XSMEM  (2 * BUFB)

__device__ __forceinline__ void stage_chunk(uint32_t sb, int buf, int ch,
                                            int m0, int n0, int tid) {
    uint32_t base = sb + buf * BUFB;
#pragma unroll
    for (int s = 0; s < 4; s++) {
        int slot = tid + s * 256;
        int row = slot >> 3, c = slot & 7;
        const char* gh = (const char*)(g_xh + (size_t)(m0 + row) * INSZ + ch * 64) + c * 16;
        const char* gl = (const char*)(g_xl + (size_t)(m0 + row) * INSZ + ch * 64) + c * 16;
        CP16(base + row * ROWB + c * 16, gh);
        CP16(base + ATILEB + row * ROWB + c * 16, gl);
    }
#pragma unroll
    for (int s = 0; s < 2; s++) {
        int slot = tid + s * 256;
        int row = slot >> 3, c = slot & 7;
        const char* gh = (const char*)(g_wth + (size_t)(n0 + row) * INSZ + ch * 64) + c * 16;
        const char* gl = (const char*)(g_wtl + (size_t)(n0 + row) * INSZ + ch * 64) + c * 16;
        CP16(base + 2 * ATILEB + row * ROWB + c * 16, gh);
        CP16(base + 2 * ATILEB + BTILEB + row * ROWB + c * 16, gl);
    }
    CPCOMMIT();
}

__global__ __launch_bounds__(256, 2) void xproj_mma() {
    extern __shared__ char sm[];
    const uint32_t sb = smem_u32(sm);
    const int tid = threadIdx.x;
    const int wid = tid >> 5;
    const int lane = tid & 31;
    const int m0 = blockIdx.y * 128;
    const int n0 = blockIdx.x * 64;
    const int wm = (wid & 3) * 32;
    const int wn = (wid >> 2) * 32;

    float acc[2][4][4];
#pragma unroll
    for (int mt = 0; mt < 2; mt++)
#pragma unroll
        for (int nt = 0; nt < 4; nt++)
#pragma unroll
            for (int q = 0; q < 4; q++) acc[mt][nt][q] = 0.0f;

    const int arow_off = (wm + (lane & 15)) * ROWB + ((lane >> 4) * 8) * 2;
    const int brow_base = wn + (lane & 7) + ((lane >> 4) << 3);
    const int bk_off = (((lane >> 3) & 1) * 8) * 2;

    stage_chunk(sb, 0, 0, m0, n0, tid);

    for (int ch = 0; ch < 8; ch++) {
        const int buf = ch & 1;
        if (ch < 7) {
            stage_chunk(sb, buf ^ 1, ch + 1, m0, n0, tid);
            CPWAIT(1);
        } else {
            CPWAIT(0);
        }
        __syncthreads();

        const uint32_t Ah = sb + buf * BUFB;
        const uint32_t Al = Ah + ATILEB;
        const uint32_t Bh = Ah + 2 * ATILEB;
        const uint32_t Bl = Bh + BTILEB;

#pragma unroll
        for (int k16 = 0; k16 < 4; k16++) {
            const int kb = k16 * 32;
            uint32_t ah[2][4], al[2][4];
#pragma unroll
            for (int mt = 0; mt < 2; mt++) {
                ldsm4(Ah + arow_off + mt * 16 * ROWB + kb, ah[mt]);
                ldsm4(Al + arow_off + mt * 16 * ROWB + kb, al[mt]);
            }
            uint32_t bh[4][2], bl[4][2];
#pragma unroll
            for (int ng = 0; ng < 2; ng++) {
                uint32_t r[4];
                ldsm4(Bh + (brow_base + ng * 16) * ROWB + bk_off + kb, r);
                bh[ng * 2][0] = r[0]; bh[ng * 2][1] = r[1];
                bh[ng * 2 + 1][0] = r[2]; bh[ng * 2 + 1][1] = r[3];
                ldsm4(Bl + (brow_base + ng * 16) * ROWB + bk_off + kb, r);
                bl[ng * 2][0] = r[0]; bl[ng * 2][1] = r[1];
                bl[ng * 2 + 1][0] = r[2]; bl[ng * 2 + 1][1] = r[3];
            }
#pragma unroll
            for (int mt = 0; mt < 2; mt++)
#pragma unroll
                for (int nt = 0; nt < 4; nt++) {
                    mma16816(acc[mt][nt], ah[mt], bh[nt][0], bh[nt][1]);
                    mma16816(acc[mt][nt], ah[mt], bl[nt][0], bl[nt][1]);
                    mma16816(acc[mt][nt], al[mt], bh[nt][0], bh[nt][1]);
                }
        }
        __syncthreads();
    }

#pragma unroll
    for (int mt = 0; mt < 2; mt++)
#pragma unroll
        for (int nt = 0; nt < 4; nt++) {
            int row = m0 + wm + mt * 16 + (lane >> 2);
            int col = n0 + wn + nt * 8 + (lane & 3) * 2;
            float* p0 = &g_xproj[(size_t)row * G4 + col];
            *(float2*)p0 = make_float2(acc[mt][nt][0], acc[mt][nt][1]);
            *(float2*)(p0 + (size_t)8 * G4) = make_float2(acc[mt][nt][2], acc[mt][nt][3]);
        }
}

// ---------------- kernel 2: persistent LSTM (v3: NO split-K reduce) --------
// Warp wid computes FULL K=512 for its 8 gate-cols = [i,f,g,o] x 2 j-values.
// Fragment accumulators ARE the gate sums; a lane-pair shfl localizes all 4
// gates of one (b,j) per thread. No red buffer, no reduce sync.
#define WROWB 1040
#define OFF_WHH 0
#define OFF_WHL (OFF_WHH + 64 * WROWB)      // 66560
#define OFF_HSH (OFF_WHL + 64 * WROWB)      // 133120
#define OFF_HSL (OFF_HSH + 16 * WROWB)      // 149760
#define LSMEM   (OFF_HSL + 16 * WROWB)      // 166400

__global__ __launch_bounds__(256, 1) void lstm_persist(
    const float* __restrict__ bias, const float* __restrict__ h0,
    const float* __restrict__ c0,   float* __restrict__ out) {
    extern __shared__ char sm[];
    const uint32_t sb = smem_u32(sm);

    const int tid  = threadIdx.x;
    const int wid  = tid >> 5;
    const int lane = tid & 31;
    const int jt = blockIdx.x & 31, bt = blockIdx.x >> 5;
    const int j0 = jt * 16, b0 = bt * 16;
    unsigned* cnt = &g_cnt4[bt][0];

    // ---- this thread's (b, j) ownership (from the m16n8 frag layout) ----
    // even lane: owns (i,f); handles row r.  odd lane: owns (g,o); row r+8.
    const int r = lane >> 2;
    const int myb = (lane & 1) ? (r + 8) : r;
    const int myjl = wid * 2 + ((lane >> 1) & 1);   // 0..15
    const int b = b0 + myb;
    const int j = j0 + myjl;

    // init h0 as bf16 hi/lo split (one store per thread covers 16x16 slice:
    // thread set covers all (myb, myjl) pairs: 16 b x 16 j? 256 threads,
    // each (b, j) appears exactly twice (two jt? no) -- cover via tid map:
    {
        int ib = tid >> 4, ij = tid & 15;       // full 16x16 coverage
        float hv = h0[(size_t)(b0 + ib) * HSZ + j0 + ij];
        __nv_bfloat16 hh = __float2bfloat16(hv);
        st_bf16_cg(&g_hbh[0][(b0 + ib) * HSZ + j0 + ij], hh);
        st_bf16_cg(&g_hbl[0][(b0 + ib) * HSZ + j0 + ij],
                   __float2bfloat16(hv - __bfloat162float(hh)));
    }

    // stage W_hh slice (64 cg-rows x 512 k, hi+lo) into smem once
    for (int it = 0; it < 16; it++) {
        int slot = tid + it * 256;
        int row = slot >> 6, c16 = slot & 63;
        size_t goff = ((size_t)(jt * 64 + row)) * HSZ + c16 * 8;
        *(uint4*)(sm + OFF_WHH + row * WROWB + c16 * 16) = *(const uint4*)(g_whh_h + goff);
        *(uint4*)(sm + OFF_WHL + row * WROWB + c16 * 16) = *(const uint4*)(g_whh_l + goff);
    }

    float cc = c0[(size_t)b * HSZ + j];
    const float bi = bias[j], bf = bias[j + HSZ];
    const float bg = bias[j + 2 * HSZ], bo = bias[j + 3 * HSZ];

    // ldsm address components
    const int arow_off = (lane & 15) * WROWB + ((lane >> 4) * 8) * 2;
    const int brow = wid * 8 + (lane & 7);
    const int bk_off = (((lane >> 3) & 1) * 8) * 2;

    __syncthreads();
    if (tid == 0) {
        __threadfence();
        unsigned tk = atomicAdd(cnt, 1u) + 1u;
        unsigned target = (tk + (GRP - 1)) & ~(unsigned)(GRP - 1);
        while (*((volatile unsigned*)cnt) < target) { }
        __threadfence();
    }
    __syncthreads();

    for (int t = 0; t < SEQ; t++) {
        const int cur = t & 1;

        // prefetch this thread's 4 gate xp values (consumed post-gemm)
        const float* xp = g_xproj + ((size_t)b * SEQ + t) * G4 + j;
        float xi = __ldg(xp);
        float xf = __ldg(xp + HSZ);
        float xg = __ldg(xp + 2 * HSZ);
        float xo = __ldg(xp + 3 * HSZ);

        // stage h (16 rows x 512 j, hi+lo) block-cooperatively
#pragma unroll
        for (int it = 0; it < 4; it++) {
            int slot = tid + it * 256;
            int row = slot >> 6, c16 = slot & 63;
            size_t goff = (size_t)(b0 + row) * HSZ + c16 * 8;
            uint4 vh = __ldcg((const uint4*)(g_hbh[cur] + goff));
            uint4 vl = __ldcg((const uint4*)(g_hbl[cur] + goff));
            *(uint4*)(sm + OFF_HSH + row * WROWB + c16 * 16) = vh;
            *(uint4*)(sm + OFF_HSL + row * WROWB + c16 * 16) = vl;
        }
        __syncthreads();

        // gemm: full K=512 for this warp's 8 gate-cols; no partials
        float acc[4];
        acc[0] = acc[1] = acc[2] = acc[3] = 0.0f;

#pragma unroll 4
        for (int k16 = 0; k16 < 32; k16++) {
            const int kb = k16 * 32;
            uint32_t ah[4], al[4];
            ldsm4(sb + OFF_HSH + arow_off + kb, ah);
            ldsm4(sb + OFF_HSL + arow_off + kb, al);
            uint32_t bh0, bh1, bl0, bl1;
            ldsm2(sb + OFF_WHH + brow * WROWB + bk_off + kb, bh0, bh1);
            ldsm2(sb + OFF_WHL + brow * WROWB + bk_off + kb, bl0, bl1);
            mma16816(acc, ah, bh0, bh1);
            mma16816(acc, ah, bl0, bl1);
            mma16816(acc, al, bh0, bh1);
        }

        // localize 4 gates of (b, j) via lane-pair exchange (xor 1)
        float oA0 = __shfl_xor_sync(0xFFFFFFFFu, acc[0], 1);
        float oA1 = __shfl_xor_sync(0xFFFFFFFFu, acc[1], 1);
        float oB0 = __shfl_xor_sync(0xFFFFFFFFu, acc[2], 1);
        float oB1 = __shfl_xor_sync(0xFFFFFFFFu, acc[3], 1);
        float si, sf, sg, so;
        if ((lane & 1) == 0) {           // row r: own i,f; partner g,o
            si = acc[0]; sf = acc[1]; sg = oA0; so = oA1;
        } else {                         // row r+8: partner i,f; own g,o
            si = oB0; sf = oB1; sg = acc[2]; so = acc[3];
        }

        float gi = si + xi + bi, gf = sf + xf + bf;
        float gg = sg + xg + bg, go = so + xo + bo;
        float iv = fast_sigmoid(gi), fv = fast_sigmoid(gf);
        float gv = fast_tanh(gg),    ov = fast_sigmoid(go);
        cc = fv * cc + iv * gv;
        float hv = ov * fast_tanh(cc);

        // publish h as bf16 split (cross-CTA), then fp32 output
        {
            __nv_bfloat16 hh = __float2bfloat16(hv);
            st_bf16_cg(&g_hbh[cur ^ 1][b * HSZ + j], hh);
            st_bf16_cg(&g_hbl[cur ^ 1][b * HSZ + j],
                       __float2bfloat16(hv - __bfloat162float(hh)));
        }
        out[((size_t)b * SEQ + t) * HSZ + j] = hv;
        if (t == SEQ - 1) {
            out[(size_t)BATCH * SEQ * HSZ + (size_t)b * HSZ + j] = hv;
            out[(size_t)BATCH * SEQ * HSZ + BATCH * HSZ + (size_t)b * HSZ + j] = cc;
        }

        // per-bt-group barrier (32 arrivals, monotonic: replay-safe)
        __syncthreads();
        if (tid == 0) {
            __threadfence();
            unsigned tk = atomicAdd(cnt, 1u) + 1u;
            unsigned target = (tk + (GRP - 1)) & ~(unsigned)(GRP - 1);
            while (*((volatile unsigned*)cnt) < target) { }
            __threadfence();
        }
        __syncthreads();
    }
}

// ---------------- launch ----------------------------------------------------
extern "C" void kernel_launch(void* const* d_in, const int* in_sizes, int n_in,
                              void* d_out, int out_size) {
    const float* x    = (const float*)d_in[0];
    const float* wih  = (const float*)d_in[1];
    const float* whh  = (const float*)d_in[2];
    const float* bias = (const float*)d_in[3];
    const float* h0   = (const float*)d_in[4];
    const float* c0   = (const float*)d_in[5];
    float* out = (float*)d_out;

    cudaFuncSetAttribute(xproj_mma, cudaFuncAttributeMaxDynamicSharedMemorySize,
                         XSMEM);
    cudaFuncSetAttribute(lstm_persist, cudaFuncAttributeMaxDynamicSharedMemorySize,
                         LSMEM);

    conv_x<<<65536, 256>>>(x);
    conv_w<<<4096, 256>>>(wih);
    conv_whh<<<4096, 256>>>(whh);
    xproj_mma<<<dim3(32, 256), 256, XSMEM>>>();
    lstm_persist<<<NCTA, 256, LSMEM>>>(bias, h0, c0, out);
}

// round 17
// speedup vs baseline: 1.2705x; 1.2705x over previous
#include <cuda_runtime.h>
#include <cuda_bf16.h>
#include <cstdint>
#include <math.h>

#define BATCH 64
#define SEQ   512
#define INSZ  512
#define HSZ   512
#define G4    2048   // 4*HSZ
#define NCTA  128
#define GRP   32     // CTAs per bt-group barrier

// ---------------- scratch (device globals; no allocation allowed) ----------
__device__ float g_xproj[(size_t)BATCH * SEQ * G4];      // x @ W_ih fp32
__device__ unsigned g_cnt4[4][32];                       // group counters
__device__ __nv_bfloat16 g_xh[(size_t)BATCH * SEQ * INSZ];   // x hi
__device__ __nv_bfloat16 g_xl[(size_t)BATCH * SEQ * INSZ];   // x lo
__device__ __nv_bfloat16 g_wth[(size_t)G4 * INSZ];           // W_ih^T hi [n][k]
__device__ __nv_bfloat16 g_wtl[(size_t)G4 * INSZ];           // W_ih^T lo
__device__ __nv_bfloat16 g_whh_h[(size_t)G4 * HSZ];          // W_hh rearranged hi [cg][k]
__device__ __nv_bfloat16 g_whh_l[(size_t)G4 * HSZ];          // W_hh rearranged lo
__device__ __nv_bfloat16 g_hbh[2][BATCH * HSZ];              // h hi ping-pong [b][j]
__device__ __nv_bfloat16 g_hbl[2][BATCH * HSZ];              // h lo ping-pong [b][j]

// ---------------- fast activations -----------------------------------------
__device__ __forceinline__ float ex2f(float x) {
    float y; asm("ex2.approx.f32 %0, %1;" : "=f"(y) : "f"(x)); return y;
}
__device__ __forceinline__ float rcpf(float x) {
    float y; asm("rcp.approx.f32 %0, %1;" : "=f"(y) : "f"(x)); return y;
}
#define LOG2E 1.4426950408889634f
__device__ __forceinline__ float fast_sigmoid(float x) {
    return rcpf(1.0f + ex2f(-x * LOG2E));
}
__device__ __forceinline__ float fast_tanh(float x) {
    float a = fabsf(x);
    float t = ex2f(-2.0f * LOG2E * a);
    float r = 1.0f - 2.0f * t * rcpf(1.0f + t);
    return copysignf(r, x);
}

// ---------------- mma.sync / ldmatrix / cp.async helpers (plain sm_103) ----
__device__ __forceinline__ uint32_t smem_u32(const void* p) {
    uint32_t a;
    asm("{ .reg .u64 t; cvta.to.shared.u64 t, %1; cvt.u32.u64 %0, t; }"
        : "=r"(a) : "l"(p));
    return a;
}
__device__ __forceinline__ void ldsm4(uint32_t addr, uint32_t r[4]) {
    asm volatile("ldmatrix.sync.aligned.m8n8.x4.shared.b16 {%0,%1,%2,%3}, [%4];"
                 : "=r"(r[0]), "=r"(r[1]), "=r"(r[2]), "=r"(r[3]) : "r"(addr));
}
__device__ __forceinline__ void mma16816(float c[4], const uint32_t a[4],
                                         uint32_t b0, uint32_t b1) {
    asm volatile(
        "mma.sync.aligned.m16n8k16.row.col.f32.bf16.bf16.f32 "
        "{%0,%1,%2,%3}, {%4,%5,%6,%7}, {%8,%9}, {%0,%1,%2,%3};"
        : "+f"(c[0]), "+f"(c[1]), "+f"(c[2]), "+f"(c[3])
        : "r"(a[0]), "r"(a[1]), "r"(a[2]), "r"(a[3]), "r"(b0), "r"(b1));
}
#define CP16(s, g) asm volatile("cp.async.cg.shared.global [%0], [%1], 16;" :: "r"(s), "l"(g))
#define CPCOMMIT() asm volatile("cp.async.commit_group;" ::: "memory")
#define CPWAIT(n)  asm volatile("cp.async.wait_group %0;" :: "n"(n) : "memory")

__device__ __forceinline__ void st_bf16_cg(__nv_bfloat16* p, __nv_bfloat16 v) {
    unsigned short u = *reinterpret_cast<unsigned short*>(&v);
    asm volatile("st.global.cg.u16 [%0], %1;" :: "l"(p), "h"(u) : "memory");
}
__device__ __forceinline__ unsigned ld_acq(const unsigned* p) {
    unsigned v;
    asm volatile("ld.acquire.gpu.u32 %0, [%1];" : "=r"(v) : "l"(p) : "memory");
    return v;
}

// ---------------- prologue conversions -------------------------------------
__global__ void conv_x(const float* __restrict__ X) {
    size_t i = (size_t)blockIdx.x * blockDim.x + threadIdx.x;
    float v = X[i];
    __nv_bfloat16 h = __float2bfloat16(v);
    g_xh[i] = h;
    g_xl[i] = __float2bfloat16(v - __bfloat162float(h));
}
// fused: W_ih transpose-split AND W_hh rearrange-split (same index space)
__global__ void conv_weights(const float* __restrict__ Wih,
                             const float* __restrict__ Whh) {
    int idx = blockIdx.x * blockDim.x + threadIdx.x;  // k*2048 + col
    int k = idx >> 11, col = idx & 2047;
    {
        float v = Wih[idx];
        __nv_bfloat16 h = __float2bfloat16(v);
        g_wth[(size_t)col * INSZ + k] = h;
        g_wtl[(size_t)col * INSZ + k] = __float2bfloat16(v - __bfloat162float(h));
    }
    {
        int gate = col >> 9, rem = col & 511;
        int jt = rem >> 4, jl = rem & 15;
        size_t cg = (size_t)(jt * 64 + gate * 16 + jl);
        float v = Whh[idx];
        __nv_bfloat16 h = __float2bfloat16(v);
        g_whh_h[cg * HSZ + k] = h;
        g_whh_l[cg * HSZ + k] = __float2bfloat16(v - __bfloat162float(h));
    }
}

// ---------------- kernel 1: x_proj via mma.sync (R14 proven) ---------------
#define ROWB   144              // 64 bf16 + 8 pad = 144B
#define ATILEB (128 * ROWB)     // 18432
#define BTILEB (64 * ROWB)      // 9216
#define BUFB   (2 * ATILEB + 2 * BTILEB)   // 55296: Ah, Al, Bh, Bl
#define XSMEM  (2 * BUFB)       // 110592 -> 2 CTAs/SM

__device__ __forceinline__ void stage_chunk(uint32_t sb, int buf, int ch,
                                            int m0, int n0, int tid) {
    uint32_t base = sb + buf * BUFB;
#pragma unroll
    for (int s = 0; s < 4; s++) {
        int slot = tid + s * 256;
        int row = slot >> 3, c = slot & 7;
        const char* gh = (const char*)(g_xh + (size_t)(m0 + row) * INSZ + ch * 64) + c * 16;
        const char* gl = (const char*)(g_xl + (size_t)(m0 + row) * INSZ + ch * 64) + c * 16;
        CP16(base + row * ROWB + c * 16, gh);
        CP16(base + ATILEB + row * ROWB + c * 16, gl);
    }
#pragma unroll
    for (int s = 0; s < 2; s++) {
        int slot = tid + s * 256;
        int row = slot >> 3, c = slot & 7;
        const char* gh = (const char*)(g_wth + (size_t)(n0 + row) * INSZ + ch * 64) + c * 16;
        const char* gl = (const char*)(g_wtl + (size_t)(n0 + row) * INSZ + ch * 64) + c * 16;
        CP16(base + 2 * ATILEB + row * ROWB + c * 16, gh);
        CP16(base + 2 * ATILEB + BTILEB + row * ROWB + c * 16, gl);
    }
    CPCOMMIT();
}

__global__ __launch_bounds__(256, 2) void xproj_mma() {
    extern __shared__ char sm[];
    const uint32_t sb = smem_u32(sm);
    const int tid = threadIdx.x;
    const int wid = tid >> 5;
    const int lane = tid & 31;
    const int m0 = blockIdx.y * 128;
    const int n0 = blockIdx.x * 64;
    const int wm = (wid & 3) * 32;
    const int wn = (wid >> 2) * 32;

    float acc[2][4][4];
#pragma unroll
    for (int mt = 0; mt < 2; mt++)
#pragma unroll
        for (int nt = 0; nt < 4; nt++)
#pragma unroll
            for (int q = 0; q < 4; q++) acc[mt][nt][q] = 0.0f;

    const int arow_off = (wm + (lane & 15)) * ROWB + ((lane >> 4) * 8) * 2;
    const int brow_base = wn + (lane & 7) + ((lane >> 4) << 3);
    const int bk_off = (((lane >> 3) & 1) * 8) * 2;

    stage_chunk(sb, 0, 0, m0, n0, tid);

    for (int ch = 0; ch < 8; ch++) {
        const int buf = ch & 1;
        if (ch < 7) {
            stage_chunk(sb, buf ^ 1, ch + 1, m0, n0, tid);
            CPWAIT(1);
        } else {
            CPWAIT(0);
        }
        __syncthreads();

        const uint32_t Ah = sb + buf * BUFB;
        const uint32_t Al = Ah + ATILEB;
        const uint32_t Bh = Ah + 2 * ATILEB;
        const uint32_t Bl = Bh + BTILEB;

#pragma unroll
        for (int k16 = 0; k16 < 4; k16++) {
            const int kb = k16 * 32;
            uint32_t ah[2][4], al[2][4];
#pragma unroll
            for (int mt = 0; mt < 2; mt++) {
                ldsm4(Ah + arow_off + mt * 16 * ROWB + kb, ah[mt]);
                ldsm4(Al + arow_off + mt * 16 * ROWB + kb, al[mt]);
            }
            uint32_t bh[4][2], bl[4][2];
#pragma unroll
            for (int ng = 0; ng < 2; ng++) {
                uint32_t r[4];
                ldsm4(Bh + (brow_base + ng * 16) * ROWB + bk_off + kb, r);
                bh[ng * 2][0] = r[0]; bh[ng * 2][1] = r[1];
                bh[ng * 2 + 1][0] = r[2]; bh[ng * 2 + 1][1] = r[3];
                ldsm4(Bl + (brow_base + ng * 16) * ROWB + bk_off + kb, r);
                bl[ng * 2][0] = r[0]; bl[ng * 2][1] = r[1];
                bl[ng * 2 + 1][0] = r[2]; bl[ng * 2 + 1][1] = r[3];
            }
#pragma unroll
            for (int mt = 0; mt < 2; mt++)
#pragma unroll
                for (int nt = 0; nt < 4; nt++) {
                    mma16816(acc[mt][nt], ah[mt], bh[nt][0], bh[nt][1]);
                    mma16816(acc[mt][nt], ah[mt], bl[nt][0], bl[nt][1]);
                    mma16816(acc[mt][nt], al[mt], bh[nt][0], bh[nt][1]);
                }
        }
        __syncthreads();
    }

#pragma unroll
    for (int mt = 0; mt < 2; mt++)
#pragma unroll
        for (int nt = 0; nt < 4; nt++) {
            int row = m0 + wm + mt * 16 + (lane >> 2);
            int col = n0 + wn + nt * 8 + (lane & 3) * 2;
            float* p0 = &g_xproj[(size_t)row * G4 + col];
            *(float2*)p0 = make_float2(acc[mt][nt][0], acc[mt][nt][1]);
            *(float2*)(p0 + (size_t)8 * G4) = make_float2(acc[mt][nt][2], acc[mt][nt][3]);
        }
}

// ---------------- kernel 2: persistent LSTM (R14 + lighter barrier) --------
#define WROWB 1040
#define OFF_WHH 0
#define OFF_WHL (OFF_WHH + 64 * WROWB)
#define OFF_HSH (OFF_WHL + 64 * WROWB)
#define OFF_HSL (OFF_HSH + 16 * WROWB)
#define OFF_RED (OFF_HSL + 16 * WROWB)
#define OFF_B0  (OFF_RED + 32768)
#define LSMEM   (OFF_B0 + 128)

__global__ __launch_bounds__(256, 1) void lstm_persist(
    const float* __restrict__ bias, const float* __restrict__ h0,
    const float* __restrict__ c0,   float* __restrict__ out) {
    extern __shared__ char sm[];
    const uint32_t sb = smem_u32(sm);
    float* red = (float*)(sm + OFF_RED);
    unsigned* sB0 = (unsigned*)(sm + OFF_B0);

    const int tid  = threadIdx.x;
    const int wid  = tid >> 5;
    const int lane = tid & 31;
    const int jt = blockIdx.x & 31, bt = blockIdx.x >> 5;
    const int j0 = jt * 16, b0 = bt * 16;
    unsigned* cnt = &g_cnt4[bt][0];

    const int bl = tid >> 4, jl_u = tid & 15;
    const int b = b0 + bl, j = j0 + jl_u;

    // init h0 as bf16 hi/lo split
    {
        float hv = h0[(size_t)b * HSZ + j];
        __nv_bfloat16 hh = __float2bfloat16(hv);
        st_bf16_cg(&g_hbh[0][b * HSZ + j], hh);
        st_bf16_cg(&g_hbl[0][b * HSZ + j],
                   __float2bfloat16(hv - __bfloat162float(hh)));
    }

    // stage W_hh slice (64 rows x 512 k, hi+lo) into smem once
    for (int it = 0; it < 16; it++) {
        int slot = tid + it * 256;
        int row = slot >> 6, c16 = slot & 63;
        size_t goff = ((size_t)(jt * 64 + row)) * HSZ + c16 * 8;
        *(uint4*)(sm + OFF_WHH + row * WROWB + c16 * 16) = *(const uint4*)(g_whh_h + goff);
        *(uint4*)(sm + OFF_WHL + row * WROWB + c16 * 16) = *(const uint4*)(g_whh_l + goff);
    }

    float cc = c0[(size_t)b * HSZ + j];
    const float bi = bias[j], bf = bias[j + HSZ];
    const float bg = bias[j + 2 * HSZ], bo = bias[j + 3 * HSZ];

    // mma identities: warp wid owns k-slice [wid*64, wid*64+64)
    const int kbase = wid * 128;
    const int arow_off = (lane & 15) * WROWB + ((lane >> 4) * 8) * 2;
    const int brow_base = (lane & 7) + ((lane >> 4) << 3);
    const int bk_off = (((lane >> 3) & 1) * 8) * 2;

    // prologue barrier: establish round base B0 (multiple of GRP), broadcast
    __syncthreads();
    if (tid == 0) {
        __threadfence();
        unsigned tk = atomicAdd(cnt, 1u) + 1u;
        unsigned target = (tk + (GRP - 1)) & ~(unsigned)(GRP - 1);
        while (ld_acq(cnt) < target) { }
        sB0[0] = target;
    }
    __syncthreads();
    const unsigned B0 = sB0[0];

    for (int t = 0; t < SEQ; t++) {
        const int cur = t & 1;

        // prefetch x_proj contribution (consumed post-gemm)
        const float* xp = g_xproj + ((size_t)b * SEQ + t) * G4 + j;
        float xi = __ldg(xp);
        float xf = __ldg(xp + HSZ);
        float xg = __ldg(xp + 2 * HSZ);
        float xo = __ldg(xp + 3 * HSZ);

        // stage h (16 rows x 512 j, hi+lo) block-cooperatively
#pragma unroll
        for (int it = 0; it < 4; it++) {
            int slot = tid + it * 256;
            int row = slot >> 6, c16 = slot & 63;
            size_t goff = (size_t)(b0 + row) * HSZ + c16 * 8;
            uint4 vh = __ldcg((const uint4*)(g_hbh[cur] + goff));
            uint4 vl = __ldcg((const uint4*)(g_hbl[cur] + goff));
            *(uint4*)(sm + OFF_HSH + row * WROWB + c16 * 16) = vh;
            *(uint4*)(sm + OFF_HSL + row * WROWB + c16 * 16) = vl;
        }
        __syncthreads();

        // gemm: 16(b) x 64(c) x 64(k-slice), bf16-split, fp32 frags
        float acc[8][4];
#pragma unroll
        for (int nt = 0; nt < 8; nt++)
#pragma unroll
            for (int q = 0; q < 4; q++) acc[nt][q] = 0.0f;

#pragma unroll
        for (int k16 = 0; k16 < 4; k16++) {
            const int kb = kbase + k16 * 32;
            uint32_t ah[4], al[4];
            ldsm4(sb + OFF_HSH + arow_off + kb, ah);
            ldsm4(sb + OFF_HSL + arow_off + kb, al);
            uint32_t bh[8][2], blo[8][2];
#pragma unroll
            for (int ng = 0; ng < 4; ng++) {
                uint32_t r[4];
                ldsm4(sb + OFF_WHH + (brow_base + ng * 16) * WROWB + bk_off + kb, r);
                bh[ng * 2][0] = r[0]; bh[ng * 2][1] = r[1];
                bh[ng * 2 + 1][0] = r[2]; bh[ng * 2 + 1][1] = r[3];
                ldsm4(sb + OFF_WHL + (brow_base + ng * 16) * WROWB + bk_off + kb, r);
                blo[ng * 2][0] = r[0]; blo[ng * 2][1] = r[1];
                blo[ng * 2 + 1][0] = r[2]; blo[ng * 2 + 1][1] = r[3];
            }
#pragma unroll
            for (int nt = 0; nt < 8; nt++) {
                mma16816(acc[nt], ah, bh[nt][0], bh[nt][1]);
                mma16816(acc[nt], ah, blo[nt][0], blo[nt][1]);
                mma16816(acc[nt], al, bh[nt][0], bh[nt][1]);
            }
        }

        // scatter split-K partials to red [warp][gate][b][jl]
        const int r0 = lane >> 2;
        const int cbase = (lane & 3) * 2;
#pragma unroll
        for (int nt = 0; nt < 8; nt++) {
            int gate = nt >> 1;
            int jl = (nt & 1) * 8 + cbase;
            float* p = &red[(wid * 4 + gate) * 256 + r0 * 16 + jl];
            *(float2*)p = make_float2(acc[nt][0], acc[nt][1]);
            *(float2*)(p + 8 * 16) = make_float2(acc[nt][2], acc[nt][3]);
        }
        __syncthreads();

        // reduce 8 warps + pointwise LSTM cell
        float si = 0.f, sf = 0.f, sg = 0.f, so = 0.f;
#pragma unroll
        for (int w = 0; w < 8; w++) {
            const float* rp = &red[w * 1024 + bl * 16 + jl_u];
            si += rp[0];
            sf += rp[256];
            sg += rp[512];
            so += rp[768];
        }
        float gi = si + xi + bi, gf = sf + xf + bf;
        float gg = sg + xg + bg, go = so + xo + bo;
        float iv = fast_sigmoid(gi), fv = fast_sigmoid(gf);
        float gv = fast_tanh(gg),    ov = fast_sigmoid(go);
        cc = fv * cc + iv * gv;
        float hv = ov * fast_tanh(cc);

        // publish h as bf16 split (cross-CTA), then fp32 output
        {
            __nv_bfloat16 hh = __float2bfloat16(hv);
            st_bf16_cg(&g_hbh[cur ^ 1][b * HSZ + j], hh);
            st_bf16_cg(&g_hbl[cur ^ 1][b * HSZ + j],
                       __float2bfloat16(hv - __bfloat162float(hh)));
        }
        out[((size_t)b * SEQ + t) * HSZ + j] = hv;
        if (t == SEQ - 1) {
            out[(size_t)BATCH * SEQ * HSZ + (size_t)b * HSZ + j] = hv;
            out[(size_t)BATCH * SEQ * HSZ + BATCH * HSZ + (size_t)b * HSZ + j] = cc;
        }

        // ---- group barrier: arrive (tid0), per-warp acquire-poll resume ----
        __syncthreads();                 // all h stores + red reads done
        if (tid == 0) {
            __threadfence();
            atomicAdd(cnt, 1u);
        }
        const unsigned tgt = B0 + GRP * (unsigned)(t + 1);
        if (lane == 0) {
            while (ld_acq(cnt) < tgt) { }
        }
        __syncwarp();
        // no block sync: each warp resumes staging independently; hsT/red are
        // quiescent (all warps passed the pre-arrive __syncthreads).
    }
}

// ---------------- launch ----------------------------------------------------
extern "C" void kernel_launch(void* const* d_in, const int* in_sizes, int n_in,
                              void* d_out, int out_size) {
    const float* x    = (const float*)d_in[0];
    const float* wih  = (const float*)d_in[1];
    const float* whh  = (const float*)d_in[2];
    const float* bias = (const float*)d_in[3];
    const float* h0   = (const float*)d_in[4];
    const float* c0   = (const float*)d_in[5];
    float* out = (float*)d_out;

    cudaFuncSetAttribute(xproj_mma, cudaFuncAttributeMaxDynamicSharedMemorySize,
                         XSMEM);
    cudaFuncSetAttribute(lstm_persist, cudaFuncAttributeMaxDynamicSharedMemorySize,
                         LSMEM);

    conv_x<<<65536, 256>>>(x);
    conv_weights<<<4096, 256>>>(wih, whh);
    xproj_mma<<<dim3(32, 256), 256, XSMEM>>>();
    lstm_persist<<<NCTA, 256, LSMEM>>>(bias, h0, c0, out);
}